// round 7
// baseline (speedup 1.0000x reference)
#include <cuda_runtime.h>

#define BB 4
#define SS 512
#define HH 128

typedef unsigned long long u64;

__device__ __forceinline__ void ffma2(u64 &acc, u64 a, u64 b) {
    asm("fma.rn.f32x2 %0, %1, %2, %0;" : "+l"(acc) : "l"(a), "l"(b));
}
__device__ __forceinline__ u64 addf2(u64 a, u64 b) {
    u64 r; asm("add.rn.f32x2 %0, %1, %2;" : "=l"(r) : "l"(a), "l"(b)); return r;
}
__device__ __forceinline__ u64 pk2(float v) {
    u64 r; asm("mov.b64 %0, {%1, %2};" : "=l"(r) : "f"(v), "f"(v)); return r;
}
__device__ __forceinline__ float2 upk(u64 v) {
    float2 r; asm("mov.b64 {%0, %1}, %2;" : "=f"(r.x), "=f"(r.y) : "l"(v)); return r;
}

// 512 blocks x 512 threads. Block owns 4 output rows (t0..t0+3).
// Thread (hp = tid&63, e = tid>>6) owns h-pair {2hp, 2hp+1} over k-chunk e (16 k).
// 14 packed-f32x2 dot accumulators; 8 k-slices tree-combined in smem.
__global__ __launch_bounds__(512, 2) void align_kernel(
    const float* __restrict__ x, const float* __restrict__ ref,
    const float* __restrict__ Wa, const float* __restrict__ Wb,
    const float* __restrict__ b1, const float* __restrict__ W2,
    const float* __restrict__ b2, const float* __restrict__ Wp1,
    const float* __restrict__ bp1, const float* __restrict__ Wp2,
    const float* __restrict__ bp2, float* __restrict__ out)
{
    const int tid = threadIdx.x;
    const int hp  = tid & 63;        // h-pair index
    const int e   = tid >> 6;        // k-chunk 0..7
    const int g0  = blockIdx.x * 4;
    const int b   = g0 >> 9;
    const int t0  = g0 & (SS - 1);

    __shared__ u64  xdup[5][HH];        // {x,x} dup, rows t0-1 .. t0+3
    __shared__ u64  rdup[5][HH];        // {ref,ref} dup
    __shared__ u64  part[4][14][64];    // tree-combine buffer
    __shared__ float red[2][24];
    __shared__ float rowvals[4][2];

    // ---- stage rows (duplicated pairs) ----
    for (int idx = tid; idx < 5 * HH; idx += 512) {
        const int r = idx >> 7;
        const int k = idx & 127;
        int t  = t0 - 1 + r;
        int tc = t < 0 ? 0 : t;
        const size_t gi = (size_t)(b * SS + tc) * HH + k;
        xdup[r][k] = pk2(x[gi]);
        rdup[r][k] = pk2(ref[gi]);
    }
    __syncthreads();

    // ---- mainloop over this thread's 16 k ----
    u64 A[5], C[5], P[4];
    {
        const u64 ab = (e == 0) ? ((const u64*)b1)[hp]  : 0ULL;
        const u64 pb = (e == 0) ? ((const u64*)bp1)[hp] : 0ULL;
        #pragma unroll
        for (int r = 0; r < 5; r++) { A[r] = ab; C[r] = 0ULL; }
        #pragma unroll
        for (int r = 0; r < 4; r++) P[r] = pb;
    }

    const u64* __restrict__ Wa2 = (const u64*)Wa;   // [k*64 + hp]
    const u64* __restrict__ Wb2 = (const u64*)Wb;
    const u64* __restrict__ Wp  = (const u64*)Wp1;

    const int kb = e * 16;
    #pragma unroll 4
    for (int kk = 0; kk < 16; kk++) {
        const int k = kb + kk;
        const u64 wa = Wa2[k * 64 + hp];
        const u64 wb = Wb2[k * 64 + hp];
        const u64 wp = Wp [k * 64 + hp];
        const u64 x0 = xdup[0][k], x1 = xdup[1][k], x2 = xdup[2][k],
                  x3 = xdup[3][k], x4 = xdup[4][k];
        const u64 r0 = rdup[0][k], r1 = rdup[1][k], r2 = rdup[2][k],
                  r3 = rdup[3][k], r4 = rdup[4][k];
        ffma2(A[0], wa, x0); ffma2(A[1], wa, x1); ffma2(A[2], wa, x2);
        ffma2(A[3], wa, x3); ffma2(A[4], wa, x4);
        ffma2(C[0], wb, r0); ffma2(C[1], wb, r1); ffma2(C[2], wb, r2);
        ffma2(C[3], wb, r3); ffma2(C[4], wb, r4);
        ffma2(P[0], wp, x1); ffma2(P[1], wp, x2);
        ffma2(P[2], wp, x3); ffma2(P[3], wp, x4);
    }

    // ---- tree combine: 8 slices -> slice 0 ----
    if (e >= 4) {
        #pragma unroll
        for (int r = 0; r < 5; r++) { part[e - 4][r][hp] = A[r]; part[e - 4][5 + r][hp] = C[r]; }
        #pragma unroll
        for (int r = 0; r < 4; r++) part[e - 4][10 + r][hp] = P[r];
    }
    __syncthreads();
    if (e < 4) {
        #pragma unroll
        for (int r = 0; r < 5; r++) { A[r] = addf2(A[r], part[e][r][hp]); C[r] = addf2(C[r], part[e][5 + r][hp]); }
        #pragma unroll
        for (int r = 0; r < 4; r++) P[r] = addf2(P[r], part[e][10 + r][hp]);
    }
    __syncthreads();
    if (e == 2 || e == 3) {
        #pragma unroll
        for (int r = 0; r < 5; r++) { part[e - 2][r][hp] = A[r]; part[e - 2][5 + r][hp] = C[r]; }
        #pragma unroll
        for (int r = 0; r < 4; r++) part[e - 2][10 + r][hp] = P[r];
    }
    __syncthreads();
    if (e < 2) {
        #pragma unroll
        for (int r = 0; r < 5; r++) { A[r] = addf2(A[r], part[e][r][hp]); C[r] = addf2(C[r], part[e][5 + r][hp]); }
        #pragma unroll
        for (int r = 0; r < 4; r++) P[r] = addf2(P[r], part[e][10 + r][hp]);
    }
    __syncthreads();
    if (e == 1) {
        #pragma unroll
        for (int r = 0; r < 5; r++) { part[0][r][hp] = A[r]; part[0][5 + r][hp] = C[r]; }
        #pragma unroll
        for (int r = 0; r < 4; r++) part[0][10 + r][hp] = P[r];
    }
    __syncthreads();

    if (e == 0) {
        #pragma unroll
        for (int r = 0; r < 5; r++) { A[r] = addf2(A[r], part[0][r][hp]); C[r] = addf2(C[r], part[0][5 + r][hp]); }
        #pragma unroll
        for (int r = 0; r < 4; r++) P[r] = addf2(P[r], part[0][10 + r][hp]);

        // unpack
        float af[5][2], cf[5][2], pf[4][2];
        #pragma unroll
        for (int r = 0; r < 5; r++) {
            float2 u = upk(A[r]); af[r][0] = u.x; af[r][1] = u.y;
            float2 v = upk(C[r]); cf[r][0] = v.x; cf[r][1] = v.y;
        }
        #pragma unroll
        for (int r = 0; r < 4; r++) {
            float2 u = upk(P[r]);
            pf[r][0] = fmaxf(u.x, 0.f); pf[r][1] = fmaxf(u.y, 0.f);
        }

        const float2 w2p  = ((const float2*)W2)[hp];
        const float  w2a[2] = {w2p.x, w2p.y};
        const float* wq = &Wp2[6 * hp];   // [h0:0..2, h1:3..5]

        const int wid  = tid >> 5;   // 0 or 1
        const int lane = tid & 31;

        #pragma unroll
        for (int i = 0; i < 4; i++) {
            float v[6] = {0.f, 0.f, 0.f, 0.f, 0.f, 0.f};
            #pragma unroll
            for (int j = 0; j < 2; j++) {
                v[0] += fmaxf(af[i + 1][j] + cf[i + 1][j], 0.f) * w2a[j];
                v[1] += fmaxf(af[i][j]     + cf[i + 1][j], 0.f) * w2a[j];
                v[2] += fmaxf(af[i + 1][j] + cf[i][j],     0.f) * w2a[j];
                const float pj = pf[i][j];
                v[3] += pj * wq[3 * j + 0];
                v[4] += pj * wq[3 * j + 1];
                v[5] += pj * wq[3 * j + 2];
            }
            #pragma unroll
            for (int j = 0; j < 6; j++) {
                float s = v[j];
                s += __shfl_xor_sync(0xffffffffu, s, 16);
                s += __shfl_xor_sync(0xffffffffu, s, 8);
                s += __shfl_xor_sync(0xffffffffu, s, 4);
                s += __shfl_xor_sync(0xffffffffu, s, 2);
                s += __shfl_xor_sync(0xffffffffu, s, 1);
                if (lane == 0) red[wid][i * 6 + j] = s;
            }
        }
        asm volatile("bar.sync 1, 64;" ::: "memory");

        if (tid < 32) {
            float s = 0.0f;
            if (lane < 24) s = red[0][lane] + red[1][lane];
            const float s0 = __shfl_sync(0xffffffffu, s, lane * 6 + 0);
            const float s1 = __shfl_sync(0xffffffffu, s, lane * 6 + 1);
            const float s2 = __shfl_sync(0xffffffffu, s, lane * 6 + 2);
            const float s3 = __shfl_sync(0xffffffffu, s, lane * 6 + 3);
            const float s4 = __shfl_sync(0xffffffffu, s, lane * 6 + 4);
            const float s5 = __shfl_sync(0xffffffffu, s, lane * 6 + 5);
            if (lane < 4) {
                const int t = t0 + lane;
                float op_code, alpha;
                const float Ad = 1.0f / (1.0f + expf(-(s0 + b2[0])));
                if (t == 0) {
                    op_code = -1.0f; alpha = 0.0f;
                } else {
                    const float Ai   = 1.0f / (1.0f + expf(-(s1 + b2[0])));
                    const float Adel = 1.0f / (1.0f + expf(-(s2 + b2[0])));
                    const float l0 = s3 + bp2[0];
                    const float l1 = s4 + bp2[1];
                    const float l2 = s5 + bp2[2];
                    const float mx  = fmaxf(l0, fmaxf(l1, l2));
                    const float lse = mx + logf(expf(l0 - mx) + expf(l1 - mx) + expf(l2 - mx));
                    const float m   = Ad   * (l0 - lse);
                    const float ins = Ai   * (l1 - lse);
                    const float del = Adel * (l2 - lse);
                    int op;
                    if (m >= ins && m >= del) op = 0;  // first-max == jnp.argmax
                    else if (ins >= del)      op = 1;
                    else                      op = 2;
                    op_code = (float)op;
                    alpha   = Ad;
                }
                rowvals[lane][0] = op_code;
                rowvals[lane][1] = alpha;
            }
        }
    }
    __syncthreads();

    // ---- output: each thread writes one element (i = tid>>7, h = tid&127) ----
    {
        const int i = tid >> 7;
        const int h = tid & 127;
        const float fop   = rowvals[i][0];
        const float alpha = rowvals[i][1];
        const float cx = ((const float*)&xdup[i + 1][h])[0];
        const float cr = ((const float*)&rdup[i + 1][h])[0];
        const float px = ((const float*)&xdup[i][h])[0];
        float o;
        if (fop < -0.5f)      o = cx;
        else if (fop < 0.5f)  o = (1.0f - alpha) * cx + alpha * cr;
        else if (fop < 1.5f)  o = cr;
        else                  o = px;
        out[(size_t)(b * SS + t0 + i) * HH + h] = o;
    }
}

extern "C" void kernel_launch(void* const* d_in, const int* in_sizes, int n_in,
                              void* d_out, int out_size) {
    const float* x   = (const float*)d_in[0];
    const float* ref = (const float*)d_in[1];
    const float* Wa  = (const float*)d_in[2];
    const float* Wb  = (const float*)d_in[3];
    const float* b1  = (const float*)d_in[4];
    const float* W2  = (const float*)d_in[5];
    const float* b2  = (const float*)d_in[6];
    const float* Wp1 = (const float*)d_in[7];
    const float* bp1 = (const float*)d_in[8];
    const float* Wp2 = (const float*)d_in[9];
    const float* bp2 = (const float*)d_in[10];

    dim3 grid(BB * SS / 4);   // 512 blocks
    dim3 block(512);          // 64 h-pairs x 8 k-chunks
    align_kernel<<<grid, block>>>(x, ref, Wa, Wb, b1, W2, b2,
                                  Wp1, bp1, Wp2, bp2, (float*)d_out);
}